// round 2
// baseline (speedup 1.0000x reference)
#include <cuda_runtime.h>
#include <math.h>

#define NPATH 70656
#define BATCH 512
#define DIM   480
#define NIV   65       // max intervals = 64 breakpoints + 1

// ---- scratch (static device globals; no runtime allocation) ----
__device__ float g_A[(size_t)NIV * NPATH];   // 18.4 MB: slope tables per interval
__device__ float g_B[(size_t)NIV * NPATH];   // 18.4 MB: intercept tables per interval
__device__ float g_Y[BATCH * 25];            // spherical harmonics l=0..4
__device__ float g_t[BATCH];                 // radii
__device__ int   g_iv[BATCH];                // interval index per point
__device__ float g_bp[64];                   // sorted breakpoints
__device__ int   g_bk[64];                   // hidden-unit index crossing at bp[i]
__device__ int   g_nbp;
__device__ unsigned long long g_act0;        // active set as t->0+

// ---- structure tables ----
__constant__ int MUL_IN_c[3]   = {128, 64, 32};
__constant__ int ROWBASE_c[3]  = {0, 128, 320};
__constant__ int NLF_c[3][3]   = {{1,1,1},{1,3,3},{1,3,5}};
__constant__ int LFMIN_c[3][3] = {{0,1,2},{1,0,1},{2,1,0}};
__constant__ int PBASE_c[3][3] = {{0,16384,24576},{28672,36864,49152},{55296,59392,65536}};
__constant__ int QK_c[3][3]    = {{1,3,5},{3,9,15},{5,15,25}};
__constant__ int NSUM_c[3]     = {224,416,480};
__constant__ int COFF_c[3][3]  = {{0,128,192},{0,128,320},{0,128,320}};
__constant__ int BOFF_c[3][3]  = {{0,1,4},{0,3,30},{0,5,50}};
__constant__ int BTOT_c[3]     = {9,75,175};

// ============================================================
// Kernel 1: find & sort ReLU breakpoints of h(t) = relu(t*w1+b1)
// ============================================================
__global__ void k_prep(const float* __restrict__ w1,
                       const float* __restrict__ b1) {
    if (threadIdx.x != 0 || blockIdx.x != 0) return;
    float bp[64]; int bk[64]; int n = 0;
    unsigned long long act0 = 0ull;
    for (int k = 0; k < 64; k++) {
        float w = w1[k], b = b1[k];
        // active as t->0+ iff b>0, or (b==0 && w>0)
        if (b > 0.0f || (b == 0.0f && w > 0.0f)) act0 |= (1ull << k);
        if (w > 0.0f && b < 0.0f) { bp[n] = -b / w; bk[n] = k; n++; }   // turns ON
        else if (w < 0.0f && b > 0.0f) { bp[n] = -b / w; bk[n] = k; n++; } // turns OFF
    }
    // insertion sort by breakpoint
    for (int i = 1; i < n; i++) {
        float v = bp[i]; int kk = bk[i]; int j = i - 1;
        while (j >= 0 && bp[j] > v) { bp[j+1] = bp[j]; bk[j+1] = bk[j]; j--; }
        bp[j+1] = v; bk[j+1] = kk;
    }
    for (int i = 0; i < n; i++) { g_bp[i] = bp[i]; g_bk[i] = bk[i]; }
    g_nbp = n;
    g_act0 = act0;
}

// ============================================================
// Kernel 2: build per-interval tables A,B with incremental updates.
// c[z,p] = t*A[iv][p] + B[iv][p].  grid 70656/256, 256 thr.
// ============================================================
__global__ void k_tables(const float* __restrict__ w1,
                         const float* __restrict__ b1,
                         const float* __restrict__ w2,
                         const float* __restrict__ b2) {
    int p = blockIdx.x * 256 + threadIdx.x;    // NPATH divisible by 256
    __shared__ float sw1[64], sb1[64];
    __shared__ int   sbk[64];
    __shared__ int   snbp;
    __shared__ unsigned long long sact;
    if (threadIdx.x < 64) {
        sw1[threadIdx.x] = w1[threadIdx.x];
        sb1[threadIdx.x] = b1[threadIdx.x];
        sbk[threadIdx.x] = g_bk[threadIdx.x];
    }
    if (threadIdx.x == 0) { snbp = g_nbp; sact = g_act0; }
    __syncthreads();

    float A = 0.0f, Bv = b2[p];
    unsigned long long act = sact;
    for (int k = 0; k < 64; k++) {
        if ((act >> k) & 1ull) {
            float wv = w2[(size_t)k * NPATH + p];
            A  = fmaf(sw1[k], wv, A);
            Bv = fmaf(sb1[k], wv, Bv);
        }
    }
    g_A[p] = A; g_B[p] = Bv;
    int nbp = snbp;
    for (int i = 0; i < nbp; i++) {
        int k = sbk[i];
        float wv = w2[(size_t)k * NPATH + p];
        float s = (sw1[k] > 0.0f) ? 1.0f : -1.0f;  // w>0: unit turns on; w<0: off
        A  = fmaf(s * sw1[k], wv, A);
        Bv = fmaf(s * sb1[k], wv, Bv);
        g_A[(size_t)(i+1) * NPATH + p] = A;
        g_B[(size_t)(i+1) * NPATH + p] = Bv;
    }
}

// ============================================================
// Kernel 3: per-point setup — radius, interval index, SH values.
// one thread per z. grid 8 x 64 threads.
// ============================================================
__global__ void k_zsetup(const float* __restrict__ r) {
    int z = blockIdx.x * blockDim.x + threadIdx.x;
    if (z >= BATCH) return;
    float rx = r[z*3+0], ry = r[z*3+1], rz = r[z*3+2];
    float nrm = sqrtf(rx*rx + ry*ry + rz*rz);
    g_t[z] = nrm;

    int nbp = g_nbp, iv = 0;
    for (int j = 0; j < nbp; j++) iv += (nrm > g_bp[j]) ? 1 : 0;
    g_iv[z] = iv;

    float inv = 1.0f / fmaxf(nrm, 1e-9f);
    float x = rx*inv, y = ry*inv, zz = rz*inv;
    float rxy = sqrtf(fmaxf(x*x + y*y, 1e-18f));
    float cphi = x / rxy, sphi = y / rxy;
    float somx2 = sqrtf(fmaxf(1.0f - zz*zz, 1e-12f));

    float P[5][5];
    float pmm = 1.0f;
    #pragma unroll
    for (int m = 0; m <= 4; m++) {
        if (m > 0) pmm = pmm * (float)(2*m - 1) * somx2;
        P[m][m] = pmm;
        if (m + 1 <= 4) P[m+1][m] = zz * (float)(2*m + 1) * pmm;
        for (int l = m + 2; l <= 4; l++)
            P[l][m] = ((float)(2*l-1)*zz*P[l-1][m] - (float)(l+m-1)*P[l-2][m]) / (float)(l-m);
    }
    float cm[5], sm[5];
    cm[0] = 1.0f; sm[0] = 0.0f; cm[1] = cphi; sm[1] = sphi;
    #pragma unroll
    for (int m = 2; m <= 4; m++) {
        cm[m] = cm[m-1]*cphi - sm[m-1]*sphi;
        sm[m] = sm[m-1]*cphi + cm[m-1]*sphi;
    }
    const float INV4PI = 0.07957747154594767f;
    const float SQRT2  = 1.4142135623730951f;
    const float fact[9] = {1,1,2,6,24,120,720,5040,40320};
    int row = 0;
    #pragma unroll
    for (int l = 0; l <= 4; l++) {
        for (int m = -l; m <= l; m++) {
            int am = m < 0 ? -m : m;
            float N = sqrtf((float)(2*l+1) * INV4PI * fact[l-am] / fact[l+am]);
            float v;
            if      (m == 0) v = N * P[l][0];
            else if (m > 0)  v = SQRT2 * N * P[l][am] * cm[am];
            else             v = SQRT2 * N * P[l][am] * sm[am];
            g_Y[z*25 + row] = v;
            row++;
        }
    }
}

// ============================================================
// Kernel 4: output assembly, c evaluated on the fly from A/B tables.
// grid (224, 512): bx -> (o,u), by -> z. 256 threads.
// ============================================================
struct QPtrs { const float* q[9]; };

__global__ void k_out(QPtrs Q, float* __restrict__ out) {
    int bx = blockIdx.x;
    int z  = blockIdx.y;
    int o, u;
    if (bx < 128)      { o = 0; u = bx; }
    else if (bx < 192) { o = 1; u = bx - 128; }
    else               { o = 2; u = bx - 192; }
    const int two_lo1 = 2*o + 1;
    const int tid = threadIdx.x;

    __shared__ float Ys[25];
    __shared__ float cs[480];
    __shared__ float Bs[176];

    if (tid < 25) Ys[tid] = g_Y[z*25 + tid];

    // evaluate coefficient slice for this (z,o,u): c = t*A[iv] + B[iv]
    float t  = g_t[z];
    size_t tb = (size_t)g_iv[z] * NPATH;
    #pragma unroll
    for (int j = 0; j < 3; j++) {
        int L = MUL_IN_c[j] * NLF_c[o][j];
        size_t base = tb + PBASE_c[o][j] + (size_t)u * L;
        int coff = COFF_c[o][j];
        for (int idx = tid; idx < L; idx += 256)
            cs[coff + idx] = fmaf(t, g_A[base + idx], g_B[base + idx]);
    }
    __syncthreads();

    // B[j][i][jj][k] = sum_q Q[i][jj][qoff+q] * Y[lf^2 + q]
    for (int idx = tid; idx < BTOT_c[o]; idx += 256) {
        int j = (idx >= BOFF_c[o][1]) + (idx >= BOFF_c[o][2]);
        int rem = idx - BOFF_c[o][j];
        int two_li1 = 2*j + 1;
        int nlf = NLF_c[o][j];
        int i  = rem / (two_li1 * nlf);
        int r2 = rem % (two_li1 * nlf);
        int jj = r2 / nlf;
        int k  = r2 % nlf;
        int lfmin = LFMIN_c[o][j];
        int lf = lfmin + k;
        int qoff = k * (2*lfmin + k);
        int yoff = lf * lf;
        const float* Qp = Q.q[o*3 + j];
        int rowq = (i * two_li1 + jj) * QK_c[o][j] + qoff;
        float s = 0.0f;
        for (int q = 0; q < 2*lf + 1; q++) s += Qp[rowq + q] * Ys[yoff + q];
        Bs[idx] = s;
    }
    __syncthreads();

    float invs = rsqrtf((float)NSUM_c[o]);
    float xn0 = 3.5449077018110318f * invs;   // sqrt(4pi)/sqrt(nsum), li=0
    float xn1 = 1.7320508075688772f * xn0;    // * sqrt(3)
    float xn2 = 2.2360679774997896f * xn0;    // * sqrt(5)

    int rowbase = ROWBASE_c[o] + u * two_lo1;
    size_t obase = (size_t)z * (DIM * DIM);
    int nelem = two_lo1 * DIM;

    for (int e = tid; e < nelem; e += 256) {
        int i   = e / DIM;
        int col = e - i * DIM;
        int j, v, jj; float xn;
        if (col < 128)      { j = 0; v = col;            jj = 0;       xn = xn0; }
        else if (col < 320) { int tt = col - 128; j = 1; v = tt/3; jj = tt-3*v; xn = xn1; }
        else                { int tt = col - 320; j = 2; v = tt/5; jj = tt-5*v; xn = xn2; }
        int nlf = NLF_c[o][j];
        int two_li1 = 2*j + 1;
        const float* Bp = &Bs[BOFF_c[o][j] + (i * two_li1 + jj) * nlf];
        const float* cp = &cs[COFF_c[o][j] + v * nlf];
        float acc = 0.0f;
        for (int k = 0; k < nlf; k++) acc = fmaf(Bp[k], cp[k], acc);
        out[obase + (size_t)(rowbase + i) * DIM + col] = acc * xn;
    }
}

// ============================================================
extern "C" void kernel_launch(void* const* d_in, const int* in_sizes, int n_in,
                              void* d_out, int out_size) {
    const float* r  = (const float*)d_in[0];
    const float* w1 = (const float*)d_in[1];
    const float* b1 = (const float*)d_in[2];
    const float* w2 = (const float*)d_in[3];
    const float* b2 = (const float*)d_in[4];
    QPtrs Q;
    for (int i = 0; i < 9; i++) Q.q[i] = (const float*)d_in[5 + i];
    float* out = (float*)d_out;

    k_prep<<<1, 32>>>(w1, b1);
    k_tables<<<NPATH / 256, 256>>>(w1, b1, w2, b2);
    k_zsetup<<<8, 64>>>(r);
    k_out<<<dim3(224, BATCH), 256>>>(Q, out);
}

// round 3
// speedup vs baseline: 2.5138x; 2.5138x over previous
#include <cuda_runtime.h>
#include <math.h>

#define NPATH 70656
#define BATCH 512
#define DIM   480
#define NIV   65

// ---- scratch (static device globals; no runtime allocation) ----
__device__ float g_A[(size_t)NIV * NPATH];
__device__ float g_B[(size_t)NIV * NPATH];
__device__ float g_Y[BATCH * 25];
__device__ float g_t[BATCH];
__device__ int   g_iv[BATCH];
__device__ float g_bp[64];
__device__ int   g_bk[64];
__device__ int   g_nbp;
__device__ unsigned long long g_act0;

// ---- structure tables (used by Bs builder only; cold path) ----
__constant__ int NLF_c[3][3]   = {{1,1,1},{1,3,3},{1,3,5}};
__constant__ int LFMIN_c[3][3] = {{0,1,2},{1,0,1},{2,1,0}};
__constant__ int QK_c[3][3]    = {{1,3,5},{3,9,15},{5,15,25}};
__constant__ int BOFF_cc[3][3] = {{0,1,4},{0,3,30},{0,5,50}};
__constant__ int BTOT_cc[3]    = {9,75,175};

// ============================================================
// Kernel 1: breakpoints of h(t) = relu(t*w1+b1)
// ============================================================
__global__ void k_prep(const float* __restrict__ w1,
                       const float* __restrict__ b1) {
    if (threadIdx.x != 0 || blockIdx.x != 0) return;
    float bp[64]; int bk[64]; int n = 0;
    unsigned long long act0 = 0ull;
    for (int k = 0; k < 64; k++) {
        float w = w1[k], b = b1[k];
        if (b > 0.0f || (b == 0.0f && w > 0.0f)) act0 |= (1ull << k);
        if (w > 0.0f && b < 0.0f) { bp[n] = -b / w; bk[n] = k; n++; }
        else if (w < 0.0f && b > 0.0f) { bp[n] = -b / w; bk[n] = k; n++; }
    }
    for (int i = 1; i < n; i++) {
        float v = bp[i]; int kk = bk[i]; int j = i - 1;
        while (j >= 0 && bp[j] > v) { bp[j+1] = bp[j]; bk[j+1] = bk[j]; j--; }
        bp[j+1] = v; bk[j+1] = kk;
    }
    for (int i = 0; i < n; i++) { g_bp[i] = bp[i]; g_bk[i] = bk[i]; }
    g_nbp = n;
    g_act0 = act0;
}

// ============================================================
// Kernel 2: per-interval tables: c[z,p] = t*A[iv][p] + B[iv][p]
// ============================================================
__global__ void k_tables(const float* __restrict__ w1,
                         const float* __restrict__ b1,
                         const float* __restrict__ w2,
                         const float* __restrict__ b2) {
    int p = blockIdx.x * 256 + threadIdx.x;
    __shared__ float sw1[64], sb1[64];
    __shared__ int   sbk[64];
    __shared__ int   snbp;
    __shared__ unsigned long long sact;
    if (threadIdx.x < 64) {
        sw1[threadIdx.x] = w1[threadIdx.x];
        sb1[threadIdx.x] = b1[threadIdx.x];
        sbk[threadIdx.x] = g_bk[threadIdx.x];
    }
    if (threadIdx.x == 0) { snbp = g_nbp; sact = g_act0; }
    __syncthreads();

    float A = 0.0f, Bv = b2[p];
    unsigned long long act = sact;
    for (int k = 0; k < 64; k++) {
        if ((act >> k) & 1ull) {
            float wv = w2[(size_t)k * NPATH + p];
            A  = fmaf(sw1[k], wv, A);
            Bv = fmaf(sb1[k], wv, Bv);
        }
    }
    g_A[p] = A; g_B[p] = Bv;
    int nbp = snbp;
    for (int i = 0; i < nbp; i++) {
        int k = sbk[i];
        float wv = w2[(size_t)k * NPATH + p];
        float s = (sw1[k] > 0.0f) ? 1.0f : -1.0f;
        A  = fmaf(s * sw1[k], wv, A);
        Bv = fmaf(s * sb1[k], wv, Bv);
        g_A[(size_t)(i+1) * NPATH + p] = A;
        g_B[(size_t)(i+1) * NPATH + p] = Bv;
    }
}

// ============================================================
// Kernel 3: per-point radius, interval, spherical harmonics
// ============================================================
__global__ void k_zsetup(const float* __restrict__ r) {
    int z = blockIdx.x * blockDim.x + threadIdx.x;
    if (z >= BATCH) return;
    float rx = r[z*3+0], ry = r[z*3+1], rz = r[z*3+2];
    float nrm = sqrtf(rx*rx + ry*ry + rz*rz);
    g_t[z] = nrm;

    int nbp = g_nbp, iv = 0;
    for (int j = 0; j < nbp; j++) iv += (nrm > g_bp[j]) ? 1 : 0;
    g_iv[z] = iv;

    float inv = 1.0f / fmaxf(nrm, 1e-9f);
    float x = rx*inv, y = ry*inv, zz = rz*inv;
    float rxy = sqrtf(fmaxf(x*x + y*y, 1e-18f));
    float cphi = x / rxy, sphi = y / rxy;
    float somx2 = sqrtf(fmaxf(1.0f - zz*zz, 1e-12f));

    float P[5][5];
    float pmm = 1.0f;
    #pragma unroll
    for (int m = 0; m <= 4; m++) {
        if (m > 0) pmm = pmm * (float)(2*m - 1) * somx2;
        P[m][m] = pmm;
        if (m + 1 <= 4) P[m+1][m] = zz * (float)(2*m + 1) * pmm;
        for (int l = m + 2; l <= 4; l++)
            P[l][m] = ((float)(2*l-1)*zz*P[l-1][m] - (float)(l+m-1)*P[l-2][m]) / (float)(l-m);
    }
    float cm[5], sm[5];
    cm[0] = 1.0f; sm[0] = 0.0f; cm[1] = cphi; sm[1] = sphi;
    #pragma unroll
    for (int m = 2; m <= 4; m++) {
        cm[m] = cm[m-1]*cphi - sm[m-1]*sphi;
        sm[m] = sm[m-1]*cphi + cm[m-1]*sphi;
    }
    const float INV4PI = 0.07957747154594767f;
    const float SQRT2  = 1.4142135623730951f;
    const float fact[9] = {1,1,2,6,24,120,720,5040,40320};
    int row = 0;
    #pragma unroll
    for (int l = 0; l <= 4; l++) {
        for (int m = -l; m <= l; m++) {
            int am = m < 0 ? -m : m;
            float N = sqrtf((float)(2*l+1) * INV4PI * fact[l-am] / fact[l+am]);
            float v;
            if      (m == 0) v = N * P[l][0];
            else if (m > 0)  v = SQRT2 * N * P[l][am] * cm[am];
            else             v = SQRT2 * N * P[l][am] * sm[am];
            g_Y[z*25 + row] = v;
            row++;
        }
    }
}

// ============================================================
// Kernel 4: output assembly. CTA = (z, O). thread = column.
// ============================================================
struct QPtrs { const float* q[9]; };

// One column-section worker. All shape params compile-time.
template<int O, int J, int NLF, int MULIN, int PB, int BO>
__device__ __forceinline__ void section(int v, int jj, int col, float t,
                                        size_t tb, size_t obase,
                                        const float* __restrict__ Bs,
                                        float* __restrict__ out, float xn) {
    constexpr int ROWS    = 2*O + 1;
    constexpr int TWO_LI1 = 2*J + 1;
    constexpr int U       = (O == 0) ? 128 : (O == 1 ? 64 : 32);
    constexpr int ROWBASE = (O == 0) ? 0   : (O == 1 ? 128 : 320);
    constexpr int LJ      = MULIN * NLF;      // per-u stride of this j-block

    // B factors in registers, xnorm folded in
    float Breg[ROWS][NLF];
    #pragma unroll
    for (int i = 0; i < ROWS; i++)
        #pragma unroll
        for (int k = 0; k < NLF; k++)
            Breg[i][k] = Bs[BO + (i*TWO_LI1 + jj)*NLF + k] * xn;

    const float* __restrict__ Ap = &g_A[tb + PB + v*NLF];
    const float* __restrict__ Bp = &g_B[tb + PB + v*NLF];
    float* optr = out + obase + (size_t)ROWBASE * DIM + col;

    #pragma unroll 4
    for (int u = 0; u < U; u++) {
        float cr[NLF];
        #pragma unroll
        for (int k = 0; k < NLF; k++)
            cr[k] = fmaf(t, Ap[u*LJ + k], Bp[u*LJ + k]);
        #pragma unroll
        for (int i = 0; i < ROWS; i++) {
            float acc = 0.0f;
            #pragma unroll
            for (int k = 0; k < NLF; k++) acc = fmaf(Breg[i][k], cr[k], acc);
            optr[(size_t)(u*ROWS + i) * DIM] = acc;
        }
    }
}

template<int O>
__device__ __forceinline__ void out_body(const QPtrs& Q, float* __restrict__ out) {
    constexpr int NLF1 = (O == 0) ? 1 : 3;
    constexpr int NLF2 = (O == 0) ? 1 : (O == 1 ? 3 : 5);
    constexpr int PB0  = (O == 0) ? 0     : (O == 1 ? 28672 : 55296);
    constexpr int PB1  = (O == 0) ? 16384 : (O == 1 ? 36864 : 59392);
    constexpr int PB2  = (O == 0) ? 24576 : (O == 1 ? 49152 : 65536);
    constexpr int BO1  = (O == 0) ? 1 : (O == 1 ? 3 : 5);
    constexpr int BO2  = (O == 0) ? 4 : (O == 1 ? 30 : 50);
    constexpr float NSUM = (O == 0) ? 224.0f : (O == 1 ? 416.0f : 480.0f);

    const int z   = blockIdx.x;
    const int tid = threadIdx.x;

    __shared__ float Ys[25];
    __shared__ float Bs[176];

    if (tid < 25) Ys[tid] = g_Y[z*25 + tid];
    __syncthreads();

    // build Bs (once per CTA; tiny)
    if (tid < BTOT_cc[O]) {
        int idx = tid;
        int j = (idx >= BOFF_cc[O][1]) + (idx >= BOFF_cc[O][2]);
        int rem = idx - BOFF_cc[O][j];
        int two_li1 = 2*j + 1;
        int nlf = NLF_c[O][j];
        int i  = rem / (two_li1 * nlf);
        int r2 = rem % (two_li1 * nlf);
        int jj = r2 / nlf;
        int k  = r2 % nlf;
        int lfmin = LFMIN_c[O][j];
        int lf = lfmin + k;
        int qoff = k * (2*lfmin + k);
        int yoff = lf * lf;
        const float* Qp = Q.q[O*3 + j];
        int rowq = (i * two_li1 + jj) * QK_c[O][j] + qoff;
        float s = 0.0f;
        for (int q = 0; q < 2*lf + 1; q++) s += Qp[rowq + q] * Ys[yoff + q];
        Bs[idx] = s;
    }
    __syncthreads();

    if (tid >= 480) return;   // warp 15 idle; no more syncs below

    const float t  = g_t[z];
    const size_t tb = (size_t)g_iv[z] * NPATH;
    const size_t obase = (size_t)z * (DIM * DIM);

    const float xnb = 3.5449077018110318f * rsqrtf(NSUM);   // sqrt(4pi)/sqrt(nsum)

    if (tid < 128) {
        // j=0: warps 0-3, v = col, jj = 0
        section<O, 0, 1, 128, PB0, 0>(tid, 0, tid, t, tb, obase, Bs, out, xnb);
    } else if (tid < 320) {
        // j=1: warps 4-9
        int tt = tid - 128; int v = tt / 3; int jj = tt - 3*v;
        section<O, 1, NLF1, 64, PB1, BO1>(v, jj, tid, t, tb, obase, Bs, out,
                                          xnb * 1.7320508075688772f);
    } else {
        // j=2: warps 10-14
        int tt = tid - 320; int v = tt / 5; int jj = tt - 5*v;
        section<O, 2, NLF2, 32, PB2, BO2>(v, jj, tid, t, tb, obase, Bs, out,
                                          xnb * 2.2360679774997896f);
    }
}

__global__ void __launch_bounds__(512) k_out2(QPtrs Q, float* __restrict__ out) {
    if      (blockIdx.y == 0) out_body<0>(Q, out);
    else if (blockIdx.y == 1) out_body<1>(Q, out);
    else                      out_body<2>(Q, out);
}

// ============================================================
extern "C" void kernel_launch(void* const* d_in, const int* in_sizes, int n_in,
                              void* d_out, int out_size) {
    const float* r  = (const float*)d_in[0];
    const float* w1 = (const float*)d_in[1];
    const float* b1 = (const float*)d_in[2];
    const float* w2 = (const float*)d_in[3];
    const float* b2 = (const float*)d_in[4];
    QPtrs Q;
    for (int i = 0; i < 9; i++) Q.q[i] = (const float*)d_in[5 + i];
    float* out = (float*)d_out;

    k_prep<<<1, 32>>>(w1, b1);
    k_tables<<<NPATH / 256, 256>>>(w1, b1, w2, b2);
    k_zsetup<<<8, 64>>>(r);
    k_out2<<<dim3(BATCH, 3), 512>>>(Q, out);
}

// round 5
// speedup vs baseline: 3.9869x; 1.5860x over previous
#include <cuda_runtime.h>
#include <math.h>

#define NPATH 70656
#define BATCH 512
#define DIM   480
#define NIV   65

// ---- scratch (static device globals; no runtime allocation) ----
__device__ float g_A[(size_t)NIV * NPATH];
__device__ float g_B[(size_t)NIV * NPATH];
__device__ float g_Y[BATCH * 25];
__device__ float g_t[BATCH];
__device__ int   g_iv[BATCH];
__device__ float g_bp[64];
__device__ int   g_bk[64];
__device__ int   g_nbp;
__device__ unsigned long long g_act0;

// ---- structure tables (cold path only) ----
__constant__ int NLF_c[3][3]   = {{1,1,1},{1,3,3},{1,3,5}};
__constant__ int LFMIN_c[3][3] = {{0,1,2},{1,0,1},{2,1,0}};
__constant__ int QK_c[3][3]    = {{1,3,5},{3,9,15},{5,15,25}};
__constant__ int BOFF_cc[3][3] = {{0,1,4},{0,3,30},{0,5,50}};
__constant__ int BTOT_cc[3]    = {9,75,175};

// ============================================================
// Kernel 1: breakpoints of h(t)=relu(t*w1+b1), parallel (64 thr)
// ============================================================
__global__ void k_prep(const float* __restrict__ w1,
                       const float* __restrict__ b1) {
    int k = threadIdx.x;                     // 0..63
    float w = w1[k], b = b1[k];
    bool act0  = (b > 0.0f) || (b == 0.0f && w > 0.0f);
    bool valid = (w > 0.0f && b < 0.0f) || (w < 0.0f && b > 0.0f);
    float bp = valid ? (-b / w) : __int_as_float(0x7f800000);  // +inf if invalid

    __shared__ float sbp[64];
    __shared__ unsigned sact[2], svld[2];
    sbp[k] = bp;
    unsigned am = __ballot_sync(0xFFFFFFFFu, act0);
    unsigned vm = __ballot_sync(0xFFFFFFFFu, valid);
    if ((k & 31) == 0) { sact[k >> 5] = am; svld[k >> 5] = vm; }
    __syncthreads();

    if (valid) {
        int rank = 0;
        for (int j = 0; j < 64; j++)
            rank += (sbp[j] < bp) || (sbp[j] == bp && j < k);
        g_bp[rank] = bp;
        g_bk[rank] = k;
    }
    if (k == 0) {
        g_nbp  = __popc(svld[0]) + __popc(svld[1]);
        g_act0 = (unsigned long long)sact[0] | ((unsigned long long)sact[1] << 32);
    }
}

// ============================================================
// Kernel 2: per-interval tables: c[z,p] = t*A[iv][p] + B[iv][p]
// ============================================================
__global__ void k_tables(const float* __restrict__ w1,
                         const float* __restrict__ b1,
                         const float* __restrict__ w2,
                         const float* __restrict__ b2) {
    int p = blockIdx.x * 256 + threadIdx.x;
    __shared__ float sw1[64], sb1[64];
    __shared__ int   sbk[64];
    __shared__ int   snbp;
    __shared__ unsigned long long sact;
    if (threadIdx.x < 64) {
        sw1[threadIdx.x] = w1[threadIdx.x];
        sb1[threadIdx.x] = b1[threadIdx.x];
        sbk[threadIdx.x] = g_bk[threadIdx.x];
    }
    if (threadIdx.x == 0) { snbp = g_nbp; sact = g_act0; }
    __syncthreads();

    float A = 0.0f, Bv = b2[p];
    unsigned long long act = sact;
    for (int k = 0; k < 64; k++) {
        if ((act >> k) & 1ull) {
            float wv = w2[(size_t)k * NPATH + p];
            A  = fmaf(sw1[k], wv, A);
            Bv = fmaf(sb1[k], wv, Bv);
        }
    }
    g_A[p] = A; g_B[p] = Bv;
    int nbp = snbp;
    for (int i = 0; i < nbp; i++) {
        int k = sbk[i];
        float wv = w2[(size_t)k * NPATH + p];
        float s = (sw1[k] > 0.0f) ? 1.0f : -1.0f;
        A  = fmaf(s * sw1[k], wv, A);
        Bv = fmaf(s * sb1[k], wv, Bv);
        g_A[(size_t)(i+1) * NPATH + p] = A;
        g_B[(size_t)(i+1) * NPATH + p] = Bv;
    }
}

// ============================================================
// Kernel 3: per-point radius, interval, spherical harmonics
// ============================================================
__global__ void k_zsetup(const float* __restrict__ r) {
    int z = blockIdx.x * blockDim.x + threadIdx.x;
    if (z >= BATCH) return;
    float rx = r[z*3+0], ry = r[z*3+1], rz = r[z*3+2];
    float nrm = sqrtf(rx*rx + ry*ry + rz*rz);
    g_t[z] = nrm;

    int nbp = g_nbp, iv = 0;
    for (int j = 0; j < nbp; j++) iv += (nrm > g_bp[j]) ? 1 : 0;
    g_iv[z] = iv;

    float inv = 1.0f / fmaxf(nrm, 1e-9f);
    float x = rx*inv, y = ry*inv, zz = rz*inv;
    float rxy = sqrtf(fmaxf(x*x + y*y, 1e-18f));
    float cphi = x / rxy, sphi = y / rxy;
    float somx2 = sqrtf(fmaxf(1.0f - zz*zz, 1e-12f));

    float P[5][5];
    float pmm = 1.0f;
    #pragma unroll
    for (int m = 0; m <= 4; m++) {
        if (m > 0) pmm = pmm * (float)(2*m - 1) * somx2;
        P[m][m] = pmm;
        if (m + 1 <= 4) P[m+1][m] = zz * (float)(2*m + 1) * pmm;
        for (int l = m + 2; l <= 4; l++)
            P[l][m] = ((float)(2*l-1)*zz*P[l-1][m] - (float)(l+m-1)*P[l-2][m]) / (float)(l-m);
    }
    float cm[5], sm[5];
    cm[0] = 1.0f; sm[0] = 0.0f; cm[1] = cphi; sm[1] = sphi;
    #pragma unroll
    for (int m = 2; m <= 4; m++) {
        cm[m] = cm[m-1]*cphi - sm[m-1]*sphi;
        sm[m] = sm[m-1]*cphi + cm[m-1]*sphi;
    }
    const float INV4PI = 0.07957747154594767f;
    const float SQRT2  = 1.4142135623730951f;
    const float fact[9] = {1,1,2,6,24,120,720,5040,40320};
    int row = 0;
    #pragma unroll
    for (int l = 0; l <= 4; l++) {
        for (int m = -l; m <= l; m++) {
            int am = m < 0 ? -m : m;
            float N = sqrtf((float)(2*l+1) * INV4PI * fact[l-am] / fact[l+am]);
            float v;
            if      (m == 0) v = N * P[l][0];
            else if (m > 0)  v = SQRT2 * N * P[l][am] * cm[am];
            else             v = SQRT2 * N * P[l][am] * sm[am];
            g_Y[z*25 + row] = v;
            row++;
        }
    }
}

// ============================================================
// Kernel 4: output assembly. CTA = (z, O, sub). thread = column.
// Double-buffered prefetch over u-groups.
// ============================================================
struct QPtrs { const float* q[9]; };

template<int UF, int NLF, int LJ>
__device__ __forceinline__ void loadg(float* A, float* B,
                                      const float* __restrict__ Ap,
                                      const float* __restrict__ Bp) {
    #pragma unroll
    for (int q = 0; q < UF; q++)
        #pragma unroll
        for (int k = 0; k < NLF; k++) {
            A[q*NLF + k] = Ap[(size_t)q * LJ + k];
            B[q*NLF + k] = Bp[(size_t)q * LJ + k];
        }
}

template<int UF, int NLF, int ROWS>
__device__ __forceinline__ void computeg(const float* A, const float* B,
                                         const float Breg[ROWS][NLF],
                                         float t, float* __restrict__ optr) {
    #pragma unroll
    for (int q = 0; q < UF; q++) {
        float cr[NLF];
        #pragma unroll
        for (int k = 0; k < NLF; k++)
            cr[k] = fmaf(t, A[q*NLF + k], B[q*NLF + k]);
        #pragma unroll
        for (int i = 0; i < ROWS; i++) {
            float acc = 0.0f;
            #pragma unroll
            for (int k = 0; k < NLF; k++) acc = fmaf(Breg[i][k], cr[k], acc);
            optr[(size_t)(q*ROWS + i) * DIM] = acc;
        }
    }
}

template<int O, int J, int NLF, int MULIN, int PB, int BO>
__device__ __forceinline__ void section(int v, int jj, int col, int sub, float t,
                                        size_t tb, size_t obase,
                                        const float* __restrict__ Bs,
                                        float* __restrict__ out, float xn) {
    constexpr int ROWS    = 2*O + 1;
    constexpr int TWO_LI1 = 2*J + 1;
    constexpr int U       = (O == 0) ? 128 : (O == 1 ? 64 : 32);
    constexpr int SPLIT   = 4;
    constexpr int USUB    = U / SPLIT;
    constexpr int UF      = (NLF == 1) ? (USUB >= 16 ? 8 : 4) : (NLF == 3 ? 2 : 1);
    constexpr int ROWBASE = (O == 0) ? 0 : (O == 1 ? 128 : 320);
    constexpr int LJ      = MULIN * NLF;
    static_assert(USUB % (2*UF) == 0, "pipeline shape");

    float Breg[ROWS][NLF];
    #pragma unroll
    for (int i = 0; i < ROWS; i++)
        #pragma unroll
        for (int k = 0; k < NLF; k++)
            Breg[i][k] = Bs[BO + (i*TWO_LI1 + jj)*NLF + k] * xn;

    const float* __restrict__ Ap =
        &g_A[tb + PB + (size_t)v*NLF + (size_t)(sub*USUB)*LJ];
    const float* __restrict__ Bp =
        &g_B[tb + PB + (size_t)v*NLF + (size_t)(sub*USUB)*LJ];
    float* optr = out + obase
                + ((size_t)ROWBASE + (size_t)(sub*USUB)*ROWS) * DIM + col;

    float A0[UF*NLF], B0[UF*NLF], A1[UF*NLF], B1[UF*NLF];
    loadg<UF, NLF, LJ>(A0, B0, Ap, Bp);

    #pragma unroll 1
    for (int u0 = 0; u0 < USUB; u0 += 2*UF) {
        // prefetch group u0+UF, then compute group u0
        loadg<UF, NLF, LJ>(A1, B1, Ap + (size_t)(u0+UF)*LJ, Bp + (size_t)(u0+UF)*LJ);
        computeg<UF, NLF, ROWS>(A0, B0, Breg, t, optr + (size_t)(u0*ROWS)*DIM);
        // prefetch group u0+2UF (if any), then compute group u0+UF
        if (u0 + 2*UF < USUB)
            loadg<UF, NLF, LJ>(A0, B0, Ap + (size_t)(u0+2*UF)*LJ, Bp + (size_t)(u0+2*UF)*LJ);
        computeg<UF, NLF, ROWS>(A1, B1, Breg, t, optr + (size_t)((u0+UF)*ROWS)*DIM);
    }
}

template<int O>
__device__ __forceinline__ void out_body(const QPtrs& Q, float* __restrict__ out) {
    constexpr int NLF1 = (O == 0) ? 1 : 3;
    constexpr int NLF2 = (O == 0) ? 1 : (O == 1 ? 3 : 5);
    constexpr int PB0  = (O == 0) ? 0     : (O == 1 ? 28672 : 55296);
    constexpr int PB1  = (O == 0) ? 16384 : (O == 1 ? 36864 : 59392);
    constexpr int PB2  = (O == 0) ? 24576 : (O == 1 ? 49152 : 65536);
    constexpr int BO1  = (O == 0) ? 1 : (O == 1 ? 3 : 5);
    constexpr int BO2  = (O == 0) ? 4 : (O == 1 ? 30 : 50);
    constexpr float NSUM = (O == 0) ? 224.0f : (O == 1 ? 416.0f : 480.0f);

    const int z   = blockIdx.x;
    const int sub = blockIdx.z;
    const int tid = threadIdx.x;

    __shared__ float Ys[25];
    __shared__ float Bs[176];

    if (tid < 25) Ys[tid] = g_Y[z*25 + tid];
    __syncthreads();

    if (tid < BTOT_cc[O]) {
        int idx = tid;
        int j = (idx >= BOFF_cc[O][1]) + (idx >= BOFF_cc[O][2]);
        int rem = idx - BOFF_cc[O][j];
        int two_li1 = 2*j + 1;
        int nlf = NLF_c[O][j];
        int i  = rem / (two_li1 * nlf);
        int r2 = rem % (two_li1 * nlf);
        int jj = r2 / nlf;
        int k  = r2 % nlf;
        int lfmin = LFMIN_c[O][j];
        int lf = lfmin + k;
        int qoff = k * (2*lfmin + k);
        int yoff = lf * lf;
        const float* Qp = Q.q[O*3 + j];
        int rowq = (i * two_li1 + jj) * QK_c[O][j] + qoff;
        float s = 0.0f;
        for (int q = 0; q < 2*lf + 1; q++) s += Qp[rowq + q] * Ys[yoff + q];
        Bs[idx] = s;
    }
    __syncthreads();

    if (tid >= 480) return;

    const float t  = g_t[z];
    const size_t tb = (size_t)g_iv[z] * NPATH;
    const size_t obase = (size_t)z * (DIM * DIM);
    const float xnb = 3.5449077018110318f * rsqrtf(NSUM);

    if (tid < 128) {
        section<O, 0, 1, 128, PB0, 0>(tid, 0, tid, sub, t, tb, obase, Bs, out, xnb);
    } else if (tid < 320) {
        int tt = tid - 128; int v = tt / 3; int jj = tt - 3*v;
        section<O, 1, NLF1, 64, PB1, BO1>(v, jj, tid, sub, t, tb, obase, Bs, out,
                                          xnb * 1.7320508075688772f);
    } else {
        int tt = tid - 320; int v = tt / 5; int jj = tt - 5*v;
        section<O, 2, NLF2, 32, PB2, BO2>(v, jj, tid, sub, t, tb, obase, Bs, out,
                                          xnb * 2.2360679774997896f);
    }
}

__global__ void __launch_bounds__(512, 2) k_out2(QPtrs Q, float* __restrict__ out) {
    if      (blockIdx.y == 0) out_body<0>(Q, out);
    else if (blockIdx.y == 1) out_body<1>(Q, out);
    else                      out_body<2>(Q, out);
}

// ============================================================
extern "C" void kernel_launch(void* const* d_in, const int* in_sizes, int n_in,
                              void* d_out, int out_size) {
    const float* r  = (const float*)d_in[0];
    const float* w1 = (const float*)d_in[1];
    const float* b1 = (const float*)d_in[2];
    const float* w2 = (const float*)d_in[3];
    const float* b2 = (const float*)d_in[4];
    QPtrs Q;
    for (int i = 0; i < 9; i++) Q.q[i] = (const float*)d_in[5 + i];
    float* out = (float*)d_out;

    k_prep<<<1, 64>>>(w1, b1);
    k_tables<<<NPATH / 256, 256>>>(w1, b1, w2, b2);
    k_zsetup<<<8, 64>>>(r);
    k_out2<<<dim3(BATCH, 3, 4), 512>>>(Q, out);
}